// round 16
// baseline (speedup 1.0000x reference)
#include <cuda_runtime.h>
#include <cuda_bf16.h>
#include <cstdint>
#include <cstddef>

#define BB 2
#define TT 2048
#define DD 1024
#define HH 16
#define HD 64
#define LOG2E 1.4426950408889634f

// ---- global scratch (allocation-free) ----
__device__ __align__(16) uint32_t g_ah[32*4096*16]; // x_norm hi [slab][m][16w]
__device__ __align__(16) uint32_t g_al[32*4096*16];
__device__ __align__(16) uint32_t g_wh[32*2048*16]; // qk_w hi [slab][n][16w]
__device__ __align__(16) uint32_t g_wl[32*2048*16];
__device__ __align__(16) uint32_t g_qh[32*2048*36]; // q hi [bh][t][36w]
__device__ __align__(16) uint32_t g_ql[32*2048*36];
__device__ __align__(16) uint32_t g_kh[32*2048*36];
__device__ __align__(16) uint32_t g_kl[32*2048*36];
__device__ __align__(16) uint32_t g_vh[32*2048*36];
__device__ __align__(16) uint32_t g_vl[32*2048*36];
__device__ __align__(16) float    g_y[BB*TT*HH*HD]; // (b,t,h,d)

__device__ __forceinline__ float ex2f(float x) {
    float r; asm("ex2.approx.f32 %0, %1;" : "=f"(r) : "f"(x)); return r;
}
__device__ __forceinline__ uint32_t pk2(float f0, float f1) {
    __nv_bfloat162 h = __floats2bfloat162_rn(f0, f1);
    return *reinterpret_cast<uint32_t*>(&h);
}
__device__ __forceinline__ void split2(float f0, float f1,
                                       uint32_t& hi, uint32_t& lo) {
    float h0 = __bfloat162float(__float2bfloat16(f0));
    float h1 = __bfloat162float(__float2bfloat16(f1));
    hi = pk2(h0, h1);
    lo = pk2(f0 - h0, f1 - h1);
}
__device__ __forceinline__ void mma_bf16(float* c, const uint32_t* a,
                                         uint32_t b0, uint32_t b1) {
    asm volatile(
        "mma.sync.aligned.m16n8k16.row.col.f32.bf16.bf16.f32 "
        "{%0,%1,%2,%3}, {%4,%5,%6,%7}, {%8,%9}, {%0,%1,%2,%3};\n"
        : "+f"(c[0]), "+f"(c[1]), "+f"(c[2]), "+f"(c[3])
        : "r"(a[0]), "r"(a[1]), "r"(a[2]), "r"(a[3]), "r"(b0), "r"(b1));
}
__device__ __forceinline__ void ldsm4(uint32_t* r, uint32_t a) {
    asm volatile("ldmatrix.sync.aligned.m8n8.x4.shared.b16 {%0,%1,%2,%3}, [%4];"
        : "=r"(r[0]), "=r"(r[1]), "=r"(r[2]), "=r"(r[3]) : "r"(a));
}
__device__ __forceinline__ void ldsm4t(uint32_t* r, uint32_t a) {
    asm volatile("ldmatrix.sync.aligned.m8n8.x4.trans.shared.b16 {%0,%1,%2,%3}, [%4];"
        : "=r"(r[0]), "=r"(r[1]), "=r"(r[2]), "=r"(r[3]) : "r"(a));
}
__device__ __forceinline__ void cp16s(uint32_t sa, const uint32_t* gsrc) {
    asm volatile("cp.async.cg.shared.global [%0], [%1], 16;\n"
                 :: "r"(sa), "l"(gsrc));
}
#define CP_COMMIT() asm volatile("cp.async.commit_group;\n" ::: "memory")
#define CP_WAIT1()  asm volatile("cp.async.wait_group 1;\n" ::: "memory")
#define CP_WAIT0()  asm volatile("cp.async.wait_group 0;\n" ::: "memory")

// ---------------------------------------------------------------------------
// pack fp32 row [1024] -> hi/lo pair words, [32 slabs][M][16w]
// ---------------------------------------------------------------------------
__global__ __launch_bounds__(256)
void pack_rows(const float* __restrict__ A, uint32_t* __restrict__ Oh,
               uint32_t* __restrict__ Ol, int M) {
    const int m = blockIdx.x, tid = threadIdx.x;
    float4 v = *(const float4*)(A + (size_t)m * 1024 + tid * 4);
    uint32_t h0, l0, h1, l1;
    split2(v.x, v.y, h0, l0);
    split2(v.z, v.w, h1, l1);
    const int s = tid >> 3, w = (tid & 7) * 2;
    size_t base = ((size_t)s * M + m) * 16 + w;
    *(uint2*)(Oh + base) = make_uint2(h0, h1);
    *(uint2*)(Ol + base) = make_uint2(l0, l1);
}

// ---------------------------------------------------------------------------
// qk projection: bf16x3 mma.sync + ldmatrix. 128x128 tile, 8 warps m32xn64,
// k32 slabs double-buffered. smem rows 80B (20w). Epilogue -> [bh][t][36w].
// ---------------------------------------------------------------------------
#define PA 2560                       // words per smem array (128*20)
#define PSLAB (4*PA)
#define PROJ_SMEM (2*PSLAB*4)         // 81920 B

__device__ __forceinline__ void proj_fill(uint32_t sb, int s, int mb, int nb,
                                          int tid) {
    #pragma unroll
    for (int it = 0; it < 8; it++) {
        int idx = tid + it * 256;     // 0..2047
        int arr = idx >> 9;           // 0..3 (512 chunks each)
        int r = (idx >> 2) & 127, c = idx & 3;
        const uint32_t* g;
        if (arr < 2)
            g = (arr ? g_al : g_ah) + ((size_t)s*4096 + mb*128 + r)*16 + c*4;
        else
            g = (arr == 2 ? g_wh : g_wl) + ((size_t)s*2048 + nb*128 + r)*16 + c*4;
        cp16s(sb + (arr*PA + r*20 + c*4)*4, g);
    }
}

__global__ __launch_bounds__(256, 2)
void qk_proj_v2(const float* __restrict__ bias) {
    extern __shared__ uint32_t sm[];
    const uint32_t sbase = (uint32_t)__cvta_generic_to_shared(sm);
    const int nb = blockIdx.x, mb = blockIdx.y;
    const int tid = threadIdx.x, lane = tid & 31, wid = tid >> 5;
    const int wm = (wid & 3) * 32, wn = (wid >> 2) * 64;
    const int lr = lane >> 2, lq = lane & 3;
    const uint32_t rsel = lane & 15, khalf = (lane >> 4) * 16;

    float acc[2][8][4] = {};
    proj_fill(sbase, 0, mb, nb, tid); CP_COMMIT();

    for (int s = 0; s < 32; s++) {
        if (s + 1 < 32) {
            proj_fill(sbase + ((s+1)&1)*PSLAB*4, s+1, mb, nb, tid);
            CP_COMMIT(); CP_WAIT1();
        } else CP_WAIT0();
        __syncthreads();
        const uint32_t ab = sbase + (s & 1) * PSLAB * 4;
        #pragma unroll
        for (int ks = 0; ks < 2; ks++) {
            const uint32_t ko = ks * 32 + khalf;
            uint32_t ah[2][4], al_[2][4];
            #pragma unroll
            for (int mi = 0; mi < 2; mi++) {
                uint32_t a = ab + (wm + mi*16 + rsel) * 80 + ko;
                ldsm4(ah[mi], a);
                ldsm4(al_[mi], a + PA*4);
            }
            #pragma unroll
            for (int p = 0; p < 4; p++) {
                uint32_t bh4[4], bl4[4];
                uint32_t a = ab + 2*PA*4 + (wn + p*16 + rsel) * 80 + ko;
                ldsm4(bh4, a);
                ldsm4(bl4, a + PA*4);
                #pragma unroll
                for (int e = 0; e < 2; e++)
                    #pragma unroll
                    for (int mi = 0; mi < 2; mi++) {
                        float* c = acc[mi][p*2 + e];
                        mma_bf16(c, ah[mi],  bh4[e], bh4[e+2]);
                        mma_bf16(c, ah[mi],  bl4[e], bl4[e+2]);
                        mma_bf16(c, al_[mi], bh4[e], bh4[e+2]);
                    }
            }
        }
        __syncthreads();
    }

    #pragma unroll
    for (int nj = 0; nj < 8; nj++) {
        int n0 = nb*128 + wn + nj*8 + 2*lq;
        float2 bv = *(const float2*)(bias + n0);
        int nn = n0 & (DD - 1);
        uint32_t* dh = (n0 < DD) ? g_qh : g_kh;
        uint32_t* dl = (n0 < DD) ? g_ql : g_kl;
        int hh = nn >> 6, d2 = (nn & 63) >> 1;
        #pragma unroll
        for (int mi = 0; mi < 2; mi++)
            #pragma unroll
            for (int rh = 0; rh < 2; rh++) {
                int m0 = mb*128 + wm + mi*16 + lr + rh*8;
                int b = m0 >> 11, t = m0 & (TT - 1);
                size_t base = ((size_t)((b*HH + hh)*TT + t))*36 + d2;
                uint32_t h, l;
                split2(acc[mi][nj][rh*2] + bv.x,
                       acc[mi][nj][rh*2+1] + bv.y, h, l);
                dh[base] = h; dl[base] = l;
            }
    }
}

// ---------------------------------------------------------------------------
// v head-mix -> [bh][t][36w] hi/lo. Block per (b,t).
// ---------------------------------------------------------------------------
__global__ __launch_bounds__(256)
void mixv_v2(const float* __restrict__ xt, const float* __restrict__ vf) {
    __shared__ float xs[1024];
    __shared__ float fs[256];
    const int bt = blockIdx.x, tid = threadIdx.x;
    const int b = bt >> 11, t = bt & (TT - 1);
    *(float4*)&xs[tid*4] = *(const float4*)(xt + (size_t)bt * 1024 + tid*4);
    if (tid < 64) *(float4*)&fs[tid*4] = *(const float4*)(vf + tid*4);
    __syncthreads();
    const int o = tid * 4, i = o >> 6, d = o & 63;
    float4 a = make_float4(0.f, 0.f, 0.f, 0.f);
    #pragma unroll
    for (int j = 0; j < 16; j++) {
        float f = fs[i*16 + j];
        float4 x = *(const float4*)&xs[j*64 + d];
        a.x = fmaf(f, x.x, a.x); a.y = fmaf(f, x.y, a.y);
        a.z = fmaf(f, x.z, a.z); a.w = fmaf(f, x.w, a.w);
    }
    uint32_t h0, l0, h1, l1;
    split2(a.x, a.y, h0, l0);
    split2(a.z, a.w, h1, l1);
    size_t base = ((size_t)((b*HH + i)*TT + t))*36 + (d >> 1);
    *(uint2*)(g_vh + base) = make_uint2(h0, h1);
    *(uint2*)(g_vl + base) = make_uint2(l0, l1);
}

// ---------------------------------------------------------------------------
// causal flash attention: q-tile 128, key-tile 64, 8 warps m16xn64, bf16x3
// mma.sync + ldmatrix (V via .trans), log2-softmax on MUFU, double-buffered.
// Prefetch of slab kt+2 is issued AFTER compute+sync of slab kt (its buffer).
// ---------------------------------------------------------------------------
#define QA 4608                       // words per Q array (128*36)
#define KA 2304                       // words per K/V array (64*36)
#define ASLAB (4*KA)
#define ATTN_SMEM ((2*QA + 2*ASLAB)*4)  // 110592 B

__device__ __forceinline__ void attn_fill_kv(uint32_t sb, int bh, int kt,
                                             int tid) {
    size_t go = ((size_t)bh*TT + kt*64)*36;
    #pragma unroll
    for (int it = 0; it < 9; it++) {
        int idx = tid + it * 256;     // 0..2303
        int arr = idx / 576, o = idx - arr * 576;
        const uint32_t* g = (arr == 0) ? g_kh + go : (arr == 1) ? g_kl + go
                          : (arr == 2) ? g_vh + go : g_vl + go;
        cp16s(sb + arr*KA*4 + o*16, g + o*4);
    }
}

__global__ __launch_bounds__(256, 2)
void attn_v2() {
    extern __shared__ uint32_t sm[];
    const uint32_t sbase = (uint32_t)__cvta_generic_to_shared(sm);
    const uint32_t qb = sbase, kv0 = sbase + 2*QA*4, kv1 = kv0 + ASLAB*4;

    const int qt = 15 - (int)blockIdx.x;
    const int bh = blockIdx.y;
    const int h = bh & (HH - 1);
    const float slope2 = exp2f(-0.5f * (float)(h + 1)) * LOG2E;
    const float SC = 0.125f * LOG2E;
    const int tid = threadIdx.x, lane = tid & 31, wid = tid >> 5;
    const int lr = lane >> 2, lq = lane & 3;
    const uint32_t rsel = lane & 15, khalf = (lane >> 4) * 16;
    const int qbase = qt * 128, wrow = wid * 16;
    const int nkt = 2 * qt + 2;

    {   // group0 = Q + KV slab 0; group1 = KV slab 1
        size_t qo = ((size_t)bh*TT + qbase)*36;
        #pragma unroll
        for (int it = 0; it < 9; it++) {
            int idx = tid + it * 256;
            int arr = idx / 1152, o = idx - arr * 1152;
            cp16s(qb + arr*QA*4 + o*16, (arr ? g_ql : g_qh) + qo + o*4);
        }
        attn_fill_kv(kv0, bh, 0, tid);
        CP_COMMIT();
        attn_fill_kv(kv1, bh, 1, tid);
        CP_COMMIT();
    }

    float o[8][4] = {};
    float m_st[2] = {-1e30f, -1e30f}, l_st[2] = {0.f, 0.f};

    for (int kt = 0; kt < nkt; kt++) {
        // pending groups entering iter kt: {fill(kt), fill(kt+1)} (when present)
        if (kt + 1 < nkt) CP_WAIT1();
        else CP_WAIT0();
        __syncthreads();
        const uint32_t kb = (kt & 1) ? kv1 : kv0;
        const uint32_t vb = kb + 2*KA*4;

        // S = Q K^T
        float s[8][4] = {};
        #pragma unroll
        for (int ks = 0; ks < 4; ks++) {
            const uint32_t ko = ks * 32 + khalf;
            uint32_t qh4[4], ql4[4];
            uint32_t qa = qb + (wrow + rsel) * 144 + ko;
            ldsm4(qh4, qa);
            ldsm4(ql4, qa + QA*4);
            #pragma unroll
            for (int p = 0; p < 4; p++) {
                uint32_t kh4[4], kl4[4];
                uint32_t a = kb + (p*16 + rsel) * 144 + ko;
                ldsm4(kh4, a);
                ldsm4(kl4, a + KA*4);
                #pragma unroll
                for (int e = 0; e < 2; e++) {
                    float* c = s[p*2 + e];
                    mma_bf16(c, qh4, kh4[e], kh4[e+2]);
                    mma_bf16(c, qh4, kl4[e], kl4[e+2]);
                    mma_bf16(c, ql4, kh4[e], kh4[e+2]);
                }
            }
        }

        // scale + ALiBi + mask + online softmax (log2 domain, MUFU ex2)
        const bool partial = (kt >= 2 * qt);
        #pragma unroll
        for (int half = 0; half < 2; half++) {
            int qi = qbase + wrow + lr + half * 8;
            float tm = -1e30f;
            #pragma unroll
            for (int nj = 0; nj < 8; nj++)
                #pragma unroll
                for (int c = 0; c < 2; c++) {
                    int ki = kt*64 + nj*8 + 2*lq + c;
                    float v = fmaf(s[nj][half*2+c], SC,
                                   slope2 * (float)(ki - qi));
                    if (partial && ki > qi) v = -1e30f;
                    s[nj][half*2+c] = v;
                    tm = fmaxf(tm, v);
                }
            tm = fmaxf(tm, __shfl_xor_sync(0xffffffffu, tm, 1));
            tm = fmaxf(tm, __shfl_xor_sync(0xffffffffu, tm, 2));
            float mnew = fmaxf(m_st[half], tm);
            float alpha = ex2f(m_st[half] - mnew);
            float rsum = 0.f;
            #pragma unroll
            for (int nj = 0; nj < 8; nj++)
                #pragma unroll
                for (int c = 0; c < 2; c++) {
                    float p = ex2f(s[nj][half*2+c] - mnew);
                    s[nj][half*2+c] = p;
                    rsum += p;
                }
            rsum += __shfl_xor_sync(0xffffffffu, rsum, 1);
            rsum += __shfl_xor_sync(0xffffffffu, rsum, 2);
            l_st[half] = l_st[half] * alpha + rsum;
            m_st[half] = mnew;
            #pragma unroll
            for (int nj = 0; nj < 8; nj++) {
                o[nj][half*2+0] *= alpha;
                o[nj][half*2+1] *= alpha;
            }
        }

        // O += P V  (V B-frags via ldmatrix.trans)
        #pragma unroll
        for (int kst = 0; kst < 4; kst++) {
            uint32_t ph[4], pl[4];
            split2(s[2*kst][0],   s[2*kst][1],   ph[0], pl[0]);
            split2(s[2*kst][2],   s[2*kst][3],   ph[1], pl[1]);
            split2(s[2*kst+1][0], s[2*kst+1][1], ph[2], pl[2]);
            split2(s[2*kst+1][2], s[2*kst+1][3], ph[3], pl[3]);
            #pragma unroll
            for (int p = 0; p < 4; p++) {
                uint32_t vh4[4], vl4[4];
                uint32_t a = vb + (kst*16 + rsel) * 144 + p*32 + khalf;
                ldsm4t(vh4, a);
                ldsm4t(vl4, a + KA*4);
                #pragma unroll
                for (int e = 0; e < 2; e++) {
                    float* c = o[p*2 + e];
                    mma_bf16(c, ph, vh4[2*e], vh4[2*e+1]);
                    mma_bf16(c, ph, vl4[2*e], vl4[2*e+1]);
                    mma_bf16(c, pl, vh4[2*e], vh4[2*e+1]);
                }
            }
        }
        __syncthreads();   // all reads of buffer (kt&1) complete

        if (kt + 2 < nkt) {   // refill the buffer just vacated by slab kt
            attn_fill_kv((kt & 1) ? kv1 : kv0, bh, kt + 2, tid);
            CP_COMMIT();
        }
    }

    const int b = bh >> 4;
    #pragma unroll
    for (int half = 0; half < 2; half++) {
        int qi = qbase + wrow + lr + half * 8;
        float inv = 1.0f / l_st[half];
        #pragma unroll
        for (int nj = 0; nj < 8; nj++) {
            float2 w = make_float2(o[nj][half*2] * inv, o[nj][half*2+1] * inv);
            *(float2*)(g_y + ((size_t)((b*TT + qi)*HH + h))*HD + nj*8 + 2*lq) = w;
        }
    }
}

// ---------------------------------------------------------------------------
// final head-mix: out[b,t,i,d] = sum_j g_y[b,t,j,d]*of[i,j]
// ---------------------------------------------------------------------------
__global__ __launch_bounds__(256)
void mix_out(const float* __restrict__ fact, float* __restrict__ dst) {
    __shared__ float xs[1024];
    __shared__ float fs[256];
    const int bt = blockIdx.x, tid = threadIdx.x;
    *(float4*)&xs[tid*4] = *(const float4*)(g_y + (size_t)bt * 1024 + tid*4);
    if (tid < 64) *(float4*)&fs[tid*4] = *(const float4*)(fact + tid*4);
    __syncthreads();
    const int o = tid * 4, i = o >> 6, d = o & 63;
    float4 acc = make_float4(0.f, 0.f, 0.f, 0.f);
    #pragma unroll
    for (int j = 0; j < 16; j++) {
        float f = fs[i*16 + j];
        float4 x = *(const float4*)&xs[j*64 + d];
        acc.x = fmaf(f, x.x, acc.x); acc.y = fmaf(f, x.y, acc.y);
        acc.z = fmaf(f, x.z, acc.z); acc.w = fmaf(f, x.w, acc.w);
    }
    *(float4*)(dst + (size_t)bt * 1024 + o) = acc;
}

// ---------------------------------------------------------------------------
extern "C" void kernel_launch(void* const* d_in, const int* in_sizes, int n_in,
                              void* d_out, int out_size) {
    const float* x_norm   = (const float*)d_in[0];
    const float* xt       = (const float*)d_in[1];
    const float* qk_w     = (const float*)d_in[2];
    const float* qk_b     = (const float*)d_in[3];
    const float* v_fact   = (const float*)d_in[4];
    const float* out_fact = (const float*)d_in[5];
    float* out = (float*)d_out;

    uint32_t *p_ah, *p_al, *p_wh, *p_wl;
    cudaGetSymbolAddress((void**)&p_ah, g_ah);
    cudaGetSymbolAddress((void**)&p_al, g_al);
    cudaGetSymbolAddress((void**)&p_wh, g_wh);
    cudaGetSymbolAddress((void**)&p_wl, g_wl);
    cudaFuncSetAttribute(qk_proj_v2,
        cudaFuncAttributeMaxDynamicSharedMemorySize, PROJ_SMEM);
    cudaFuncSetAttribute(attn_v2,
        cudaFuncAttributeMaxDynamicSharedMemorySize, ATTN_SMEM);

    pack_rows<<<4096, 256>>>(x_norm, p_ah, p_al, 4096);
    pack_rows<<<2048, 256>>>(qk_w,   p_wh, p_wl, 2048);
    mixv_v2<<<BB*TT, 256>>>(xt, v_fact);
    qk_proj_v2<<<dim3(16, 32), 256, PROJ_SMEM>>>(qk_b);
    attn_v2<<<dim3(16, 32), 256, ATTN_SMEM>>>();
    mix_out<<<BB*TT, 256>>>(out_fact, out);
}